// round 3
// baseline (speedup 1.0000x reference)
#include <cuda_runtime.h>
#include <math.h>

#define LS 48
#define LTm1 47
#define NB 64      // batch
#define E 512
#define H 512
#define VT 32000
#define NROWS 3008      // 47*64 decoder (step,batch) rows
#define NROWS_PAD 3072  // padded to multiple of 128
#define NCHUNK 250      // 32000/128

// ---------------- device scratch (static, allowed) ----------------
__device__ float g_zero[NB * H];
__device__ float g_embs_src[LS * NB * E];
__device__ float g_embs_tgt[LTm1 * NB * E];
__device__ float g_Xf[LS * NB * 2048];
__device__ float g_Xb[LS * NB * 2048];
__device__ float g_Gd[LTm1 * NB * 2048];
__device__ float g_hs[LS * NB * 1024];    // [t][b][1024] fwd||bwd
__device__ float g_hsp[LS * NB * 1024];   // hs_proj [l][b][1024]
__device__ float g_cf[NB * H];
__device__ float g_cb[NB * H];
__device__ float g_cd[NB * H];
__device__ float g_od[NB * H];
__device__ float g_q[NB * 1024];
__device__ float g_ctx[NB * 1024];
__device__ float g_H[NROWS_PAD * H];      // decoder h history (rows m=t*64+b)
__device__ float g_tgt_logit[NROWS];
__device__ float g_maskv[NROWS];
__device__ float g_partial[NROWS_PAD * NCHUNK];
__device__ float g_blk[24];

__device__ __forceinline__ float sigm(float x) { return 1.f / (1.f + __expf(-x)); }

// ---------------- init: zero states + H padding ----------------
__global__ void k_init() {
    int i = blockIdx.x * blockDim.x + threadIdx.x;
    int n = NB * H;
    for (int j = i; j < n; j += gridDim.x * blockDim.x) {
        g_zero[j] = 0.f; g_cf[j] = 0.f; g_cb[j] = 0.f;
        g_cd[j] = 0.f; g_od[j] = 0.f;
        g_H[NROWS * H + j] = 0.f;   // pad rows 3008..3071 (exactly NB*H elems)
    }
}

// ---------------- embedding gather ----------------
__global__ void k_gather(const int* __restrict__ tok, const float* __restrict__ emb, int mode) {
    float* out = mode ? g_embs_tgt : g_embs_src;
    int rows = mode ? (LTm1 * NB) : (LS * NB);
    int n4 = rows * (E / 4);
    const float4* e4 = (const float4*)emb;
    float4* o4 = (float4*)out;
    for (int j = blockIdx.x * blockDim.x + threadIdx.x; j < n4; j += gridDim.x * blockDim.x) {
        int r = j >> 7;       // E/4 = 128
        int c = j & 127;
        o4[j] = e4[(size_t)tok[r] * 128 + c];
    }
}

// ---------------- generic 64x64 SGEMM: C = A @ W^T + b1 + b2 ----------------
// mode selects A/C from device globals.
__global__ void __launch_bounds__(256) k_sgemm64(int mode, const float* __restrict__ W, int ldw,
                                                 const float* __restrict__ b1, const float* __restrict__ b2,
                                                 int K) {
    __shared__ float As[16][64];
    __shared__ float Bs[16][64];
    const float* A; int lda; float* C; int ldc;
    switch (mode) {
        case 0: A = g_embs_src; lda = E;    C = g_Xf;  ldc = 2048; break;
        case 1: A = g_embs_src; lda = E;    C = g_Xb;  ldc = 2048; break;
        case 2: A = g_embs_tgt; lda = E;    C = g_Gd;  ldc = 2048; break;
        default: A = g_hs;      lda = 1024; C = g_hsp; ldc = 1024; break;
    }
    int nb = blockIdx.x, mb = blockIdx.y;
    int tid = threadIdx.x;
    int tx = tid & 15, ty = tid >> 4;
    const float* Ab = A + (size_t)mb * 64 * lda;
    const float* Wb = W + (size_t)nb * 64 * ldw;
    float acc[4][4] = {};
    for (int kb = 0; kb < K; kb += 16) {
#pragma unroll
        for (int i = 0; i < 4; i++) {
            int e = tid + 256 * i;
            int kk = e & 15, r = e >> 4;
            As[kk][r] = Ab[(size_t)r * lda + kb + kk];
            Bs[kk][r] = Wb[(size_t)r * ldw + kb + kk];
        }
        __syncthreads();
#pragma unroll
        for (int kk = 0; kk < 16; kk++) {
            float a[4], w[4];
#pragma unroll
            for (int i = 0; i < 4; i++) a[i] = As[kk][ty * 4 + i];
#pragma unroll
            for (int j = 0; j < 4; j++) w[j] = Bs[kk][tx * 4 + j];
#pragma unroll
            for (int i = 0; i < 4; i++)
#pragma unroll
                for (int j = 0; j < 4; j++) acc[i][j] += a[i] * w[j];
        }
        __syncthreads();
    }
#pragma unroll
    for (int i = 0; i < 4; i++) {
        int r = mb * 64 + ty * 4 + i;
#pragma unroll
        for (int j = 0; j < 4; j++) {
            int n = nb * 64 + tx * 4 + j;
            float v = acc[i][j];
            if (b1) v += b1[n];
            if (b2) v += b2[n];
            C[(size_t)r * ldc + n] = v;
        }
    }
}

// ---------------- encoder step (both directions), fused gates + cell ----------------
__global__ void __launch_bounds__(256) k_enc_step(int t, const float* __restrict__ Whh_f,
                                                  const float* __restrict__ Whh_b) {
    __shared__ float As[16][64];
    __shared__ float Bs[16][32];
    __shared__ float gbuf[64][33];
    int dir = blockIdx.y;
    int cu = blockIdx.x * 8;
    int tid = threadIdx.x;
    const float* Whh = dir ? Whh_b : Whh_f;
    const float* hprev; int ldh;
    if (t == 0) { hprev = g_zero; ldh = H; }
    else if (dir == 0) { hprev = g_hs + (size_t)(t - 1) * NB * 1024; ldh = 1024; }
    else { hprev = g_hs + (size_t)(LS - t) * NB * 1024 + 512; ldh = 1024; }
    int tx = tid & 15, ty = tid >> 4;
    float acc[4][2] = {};
    for (int kb = 0; kb < H; kb += 16) {
#pragma unroll
        for (int i = 0; i < 4; i++) {
            int e = tid + 256 * i;
            int kk = e & 15, b = e >> 4;
            As[kk][b] = hprev[(size_t)b * ldh + kb + kk];
        }
#pragma unroll
        for (int i = 0; i < 2; i++) {
            int e = tid + 256 * i;
            int kk = e & 15, j = e >> 4;
            int row = ((j >> 3) << 9) + cu + (j & 7);
            Bs[kk][j] = Whh[(size_t)row * H + kb + kk];
        }
        __syncthreads();
#pragma unroll
        for (int kk = 0; kk < 16; kk++) {
            float a0 = As[kk][ty * 4 + 0], a1 = As[kk][ty * 4 + 1];
            float a2 = As[kk][ty * 4 + 2], a3 = As[kk][ty * 4 + 3];
            float w0 = Bs[kk][tx * 2 + 0], w1 = Bs[kk][tx * 2 + 1];
            acc[0][0] += a0 * w0; acc[0][1] += a0 * w1;
            acc[1][0] += a1 * w0; acc[1][1] += a1 * w1;
            acc[2][0] += a2 * w0; acc[2][1] += a2 * w1;
            acc[3][0] += a3 * w0; acc[3][1] += a3 * w1;
        }
        __syncthreads();
    }
#pragma unroll
    for (int i = 0; i < 4; i++)
#pragma unroll
        for (int j = 0; j < 2; j++)
            gbuf[ty * 4 + i][tx * 2 + j] = acc[i][j];
    __syncthreads();
    const float* Xg = dir ? (g_Xb + (size_t)(LS - 1 - t) * NB * 2048)
                          : (g_Xf + (size_t)t * NB * 2048);
    float* cst = dir ? g_cb : g_cf;
    float* hs_out = dir ? (g_hs + (size_t)(LS - 1 - t) * NB * 1024 + 512)
                        : (g_hs + (size_t)t * NB * 1024);
#pragma unroll
    for (int i = 0; i < 2; i++) {
        int cid = tid + 256 * i;
        int b = cid >> 3, cl = cid & 7;
        int cell = cu + cl;
        const float* xb = Xg + (size_t)b * 2048;
        float gi = gbuf[b][cl] + xb[cell];
        float gf = gbuf[b][8 + cl] + xb[512 + cell];
        float gg = gbuf[b][16 + cl] + xb[1024 + cell];
        float go = gbuf[b][24 + cl] + xb[1536 + cell];
        float co = cst[b * H + cell];
        float cn = sigm(gf) * co + sigm(gi) * tanhf(gg);
        float hn = sigm(go) * tanhf(cn);
        cst[b * H + cell] = cn;
        hs_out[(size_t)b * 1024 + cell] = hn;
    }
}

// ---------------- decoder gates: gates = Gd[t] + o@Wih[:,512:]^T + h@Whh^T; LSTM cell ----------------
__global__ void __launch_bounds__(256) k_dec_gates(int t, const float* __restrict__ Wih,
                                                   const float* __restrict__ Whh) {
    __shared__ float As[16][64];
    __shared__ float Bs[16][32];
    __shared__ float gbuf[64][33];
    int cu = blockIdx.x * 8;
    int tid = threadIdx.x;
    int tx = tid & 15, ty = tid >> 4;
    const float* hprev = (t == 0) ? g_zero : (g_H + (size_t)(t - 1) * NB * H);
    float acc[4][2] = {};
    for (int part = 0; part < 2; part++) {
        const float* Ain = (part == 0) ? g_od : hprev;
        for (int kb = 0; kb < H; kb += 16) {
#pragma unroll
            for (int i = 0; i < 4; i++) {
                int e = tid + 256 * i;
                int kk = e & 15, b = e >> 4;
                As[kk][b] = Ain[(size_t)b * H + kb + kk];
            }
#pragma unroll
            for (int i = 0; i < 2; i++) {
                int e = tid + 256 * i;
                int kk = e & 15, j = e >> 4;
                int row = ((j >> 3) << 9) + cu + (j & 7);
                Bs[kk][j] = (part == 0) ? Wih[(size_t)row * 1024 + 512 + kb + kk]
                                        : Whh[(size_t)row * H + kb + kk];
            }
            __syncthreads();
#pragma unroll
            for (int kk = 0; kk < 16; kk++) {
                float a0 = As[kk][ty * 4 + 0], a1 = As[kk][ty * 4 + 1];
                float a2 = As[kk][ty * 4 + 2], a3 = As[kk][ty * 4 + 3];
                float w0 = Bs[kk][tx * 2 + 0], w1 = Bs[kk][tx * 2 + 1];
                acc[0][0] += a0 * w0; acc[0][1] += a0 * w1;
                acc[1][0] += a1 * w0; acc[1][1] += a1 * w1;
                acc[2][0] += a2 * w0; acc[2][1] += a2 * w1;
                acc[3][0] += a3 * w0; acc[3][1] += a3 * w1;
            }
            __syncthreads();
        }
    }
#pragma unroll
    for (int i = 0; i < 4; i++)
#pragma unroll
        for (int j = 0; j < 2; j++)
            gbuf[ty * 4 + i][tx * 2 + j] = acc[i][j];
    __syncthreads();
    const float* Xg = g_Gd + (size_t)t * NB * 2048;
#pragma unroll
    for (int i = 0; i < 2; i++) {
        int cid = tid + 256 * i;
        int b = cid >> 3, cl = cid & 7;
        int cell = cu + cl;
        const float* xb = Xg + (size_t)b * 2048;
        float gi = gbuf[b][cl] + xb[cell];
        float gf = gbuf[b][8 + cl] + xb[512 + cell];
        float gg = gbuf[b][16 + cl] + xb[1024 + cell];
        float go = gbuf[b][24 + cl] + xb[1536 + cell];
        float co = g_cd[b * H + cell];
        float cn = sigm(gf) * co + sigm(gi) * tanhf(gg);
        float hn = sigm(go) * tanhf(cn);
        g_cd[b * H + cell] = cn;
        g_H[((size_t)t * NB + b) * H + cell] = hn;
    }
}

// ---------------- skinny GEMM (M=64): mode0: q = h@Wq^T; mode1: o = tanh([ctx,h]@lin_W^T + b) ----------------
__global__ void __launch_bounds__(256) k_skinny(int mode, int t, const float* __restrict__ W, int ldw,
                                                const float* __restrict__ bias, int doTanh) {
    __shared__ float As[32][64];
    __shared__ float Ws[16][32];
    const float *A1, *A2 = nullptr; int lda1, lda2 = H, K1, K2; float* out; int ldo;
    if (mode == 0) { A1 = g_H + (size_t)t * NB * H; lda1 = H; K1 = H; K2 = 0; out = g_q; ldo = 1024; }
    else { A1 = g_ctx; lda1 = 1024; K1 = 1024; A2 = g_H + (size_t)t * NB * H; K2 = H; out = g_od; ldo = H; }
    int tid = threadIdx.x;
    int tn = tid & 15, tb = tid >> 4;
    int n0 = blockIdx.x * 16;
    float acc[4] = {};
    int KT = K1 + K2;
    for (int k0 = 0; k0 < KT; k0 += 32) {
        const float* src; int lda; int col;
        if (k0 < K1) { src = A1; lda = lda1; col = k0; }
        else { src = A2; lda = lda2; col = k0 - K1; }
#pragma unroll
        for (int i = 0; i < 8; i++) {
            int e = tid + 256 * i;
            int kk = e & 31, b = e >> 5;
            As[kk][b] = src[(size_t)b * lda + col + kk];
        }
#pragma unroll
        for (int i = 0; i < 2; i++) {
            int e = tid + 256 * i;
            int kk = e & 31, j = e >> 5;
            Ws[j][kk] = W[(size_t)(n0 + j) * ldw + k0 + kk];
        }
        __syncthreads();
#pragma unroll
        for (int kk = 0; kk < 32; kk++) {
            float w = Ws[tn][kk];
#pragma unroll
            for (int i = 0; i < 4; i++) acc[i] += As[kk][tb * 4 + i] * w;
        }
        __syncthreads();
    }
    int n = n0 + tn;
    float bv = bias ? bias[n] : 0.f;
#pragma unroll
    for (int i = 0; i < 4; i++) {
        float v = acc[i] + bv;
        if (doTanh) v = tanhf(v);
        out[(size_t)(tb * 4 + i) * ldo + n] = v;
    }
}

// ---------------- attention: score+softmax+context, one block per batch ----------------
__global__ void __launch_bounds__(256) k_dec_attn(const float* __restrict__ v) {
    __shared__ float sq[1024];
    __shared__ float sv[1024];
    __shared__ float sps[LS];
    int b = blockIdx.x, tid = threadIdx.x;
#pragma unroll
    for (int i = 0; i < 4; i++) {
        int k = tid + 256 * i;
        sq[k] = g_q[b * 1024 + k];
        sv[k] = v[k];
    }
    __syncthreads();
    int wid = tid >> 5, lane = tid & 31;
    for (int l = wid; l < LS; l += 8) {
        const float* hp = g_hsp + ((size_t)l * NB + b) * 1024;
        float s = 0.f;
        for (int k = lane; k < 1024; k += 32) s += sv[k] * tanhf(hp[k] + sq[k]);
#pragma unroll
        for (int o = 16; o; o >>= 1) s += __shfl_down_sync(0xffffffff, s, o);
        if (lane == 0) sps[l] = s;
    }
    __syncthreads();
    if (tid == 0) {
        float mx = -1e30f;
        for (int l = 0; l < LS; l++) mx = fmaxf(mx, sps[l]);
        float sm = 0.f;
        for (int l = 0; l < LS; l++) { float e = __expf(sps[l] - mx); sps[l] = e; sm += e; }
        float inv = 1.f / sm;
        for (int l = 0; l < LS; l++) sps[l] *= inv;
    }
    __syncthreads();
#pragma unroll
    for (int i = 0; i < 4; i++) {
        int k = tid + 256 * i;
        float acc = 0.f;
        for (int l = 0; l < LS; l++) acc += sps[l] * g_hs[((size_t)l * NB + b) * 1024 + k];
        g_ctx[b * 1024 + k] = acc;
    }
}

// ---------------- target logits (one warp per row) ----------------
__global__ void k_tgt(const int* __restrict__ ts, const float* __restrict__ oW,
                      const float* __restrict__ ob) {
    int gw = blockIdx.x * 8 + (threadIdx.x >> 5);
    int lane = threadIdx.x & 31;
    if (gw >= NROWS) return;
    int tok = ts[gw + NB];   // ts_out[t][b] = ts flat[m + 64]
    const float* h = g_H + (size_t)gw * H;
    const float* w = oW + (size_t)tok * H;
    float s = 0.f;
    for (int k = lane; k < H; k += 32) s += h[k] * w[k];
#pragma unroll
    for (int o = 16; o; o >>= 1) s += __shfl_down_sync(0xffffffff, s, o);
    if (lane == 0) {
        g_tgt_logit[gw] = s + ob[tok];
        g_maskv[gw] = (tok != 0) ? 1.f : 0.f;
    }
}

// ---------------- big GEMM + fused exp row-sums: H(3072x512) @ out_W^T(512x32000) ----------------
__global__ void __launch_bounds__(256, 2) k_lse(const float* __restrict__ oW,
                                                const float* __restrict__ ob) {
    __shared__ float As[16][128];
    __shared__ float Bs[16][128];
    int nb = blockIdx.x, mb = blockIdx.y;
    int tid = threadIdx.x;
    int tx = tid & 15, ty = tid >> 4;
    const float* Ab = g_H + (size_t)mb * 128 * H;
    const float* Wb = oW + (size_t)nb * 128 * H;
    float acc[8][8] = {};
    for (int kb = 0; kb < H; kb += 16) {
#pragma unroll
        for (int i = 0; i < 2; i++) {
            int e = tid + 256 * i;
            int r = e >> 2, q = e & 3;
            float4 va = *(const float4*)&Ab[(size_t)r * H + kb + q * 4];
            As[q * 4 + 0][r] = va.x; As[q * 4 + 1][r] = va.y;
            As[q * 4 + 2][r] = va.z; As[q * 4 + 3][r] = va.w;
            float4 vb = *(const float4*)&Wb[(size_t)r * H + kb + q * 4];
            Bs[q * 4 + 0][r] = vb.x; Bs[q * 4 + 1][r] = vb.y;
            Bs[q * 4 + 2][r] = vb.z; Bs[q * 4 + 3][r] = vb.w;
        }
        __syncthreads();
#pragma unroll
        for (int kk = 0; kk < 16; kk++) {
            float a[8], w[8];
#pragma unroll
            for (int i = 0; i < 8; i++) a[i] = As[kk][ty * 8 + i];
#pragma unroll
            for (int j = 0; j < 8; j++) w[j] = Bs[kk][tx * 8 + j];
#pragma unroll
            for (int i = 0; i < 8; i++)
#pragma unroll
                for (int j = 0; j < 8; j++) acc[i][j] += a[i] * w[j];
        }
        __syncthreads();
    }
    float rs[8];
#pragma unroll
    for (int i = 0; i < 8; i++) {
        float s = 0.f;
#pragma unroll
        for (int j = 0; j < 8; j++) {
            int n = nb * 128 + tx * 8 + j;
            s += __expf(acc[i][j] + ob[n]);
        }
        rs[i] = s;
    }
    __syncthreads();
    float* red = &As[0][0];   // reuse: 128 rows x 16 partials
#pragma unroll
    for (int i = 0; i < 8; i++) red[(ty * 8 + i) * 16 + tx] = rs[i];
    __syncthreads();
    if (tid < 128) {
        float s = 0.f;
#pragma unroll
        for (int x = 0; x < 16; x++) s += red[tid * 16 + x];
        g_partial[((size_t)mb * 128 + tid) * NCHUNK + nb] = s;
    }
}

// ---------------- final reductions ----------------
__global__ void k_red1() {
    __shared__ float s1[256], s2[256];
    int m = blockIdx.x * 256 + threadIdx.x;
    float v = 0.f, mk = 0.f;
    if (m < NROWS) {
        float s = 0.f;
        const float* p = g_partial + (size_t)m * NCHUNK;
        for (int c = 0; c < NCHUNK; c++) s += p[c];
        mk = g_maskv[m];
        v = (logf(s) - g_tgt_logit[m]) * mk;
    }
    s1[threadIdx.x] = v; s2[threadIdx.x] = mk;
    __syncthreads();
    for (int o = 128; o; o >>= 1) {
        if (threadIdx.x < o) { s1[threadIdx.x] += s1[threadIdx.x + o]; s2[threadIdx.x] += s2[threadIdx.x + o]; }
        __syncthreads();
    }
    if (threadIdx.x == 0) { g_blk[blockIdx.x * 2] = s1[0]; g_blk[blockIdx.x * 2 + 1] = s2[0]; }
}

__global__ void k_red2(float* out) {
    if (threadIdx.x == 0) {
        float a = 0.f, b = 0.f;
        for (int i = 0; i < 12; i++) { a += g_blk[i * 2]; b += g_blk[i * 2 + 1]; }
        out[0] = a / b;
    }
}

// ---------------- launcher ----------------
extern "C" void kernel_launch(void* const* d_in, const int* in_sizes, int n_in,
                              void* d_out, int out_size) {
    const int* xs = (const int*)d_in[0];
    const int* ts = (const int*)d_in[1];
    const float* src_emb = (const float*)d_in[2];
    const float* tgt_emb = (const float*)d_in[3];
    const float* encf_Wih = (const float*)d_in[4];
    const float* encf_Whh = (const float*)d_in[5];
    const float* encf_bih = (const float*)d_in[6];
    const float* encf_bhh = (const float*)d_in[7];
    const float* encb_Wih = (const float*)d_in[8];
    const float* encb_Whh = (const float*)d_in[9];
    const float* encb_bih = (const float*)d_in[10];
    const float* encb_bhh = (const float*)d_in[11];
    const float* dec_Wih = (const float*)d_in[12];
    const float* dec_Whh = (const float*)d_in[13];
    const float* dec_bih = (const float*)d_in[14];
    const float* dec_bhh = (const float*)d_in[15];
    const float* attn_W = (const float*)d_in[16];
    const float* attn_v = (const float*)d_in[17];
    const float* lin_W = (const float*)d_in[18];
    const float* lin_b = (const float*)d_in[19];
    const float* out_W = (const float*)d_in[20];
    const float* out_b = (const float*)d_in[21];

    k_init<<<64, 256>>>();
    k_gather<<<1024, 256>>>(xs, src_emb, 0);
    k_gather<<<1024, 256>>>(ts, tgt_emb, 1);

    // input-gate precompute GEMMs
    k_sgemm64<<<dim3(32, 48), 256>>>(0, encf_Wih, 512, encf_bih, encf_bhh, 512);
    k_sgemm64<<<dim3(32, 48), 256>>>(1, encb_Wih, 512, encb_bih, encb_bhh, 512);
    k_sgemm64<<<dim3(32, 47), 256>>>(2, dec_Wih, 1024, dec_bih, dec_bhh, 512);

    // encoder recurrence (both directions per launch)
    for (int t = 0; t < LS; t++)
        k_enc_step<<<dim3(64, 2), 256>>>(t, encf_Whh, encb_Whh);

    // hs_proj = hs @ Wk^T   (Wk = attn_W[:, 512:], ld 1536)
    k_sgemm64<<<dim3(16, 48), 256>>>(3, attn_W + 512, 1536, nullptr, nullptr, 1024);

    // decoder recurrence
    for (int t = 0; t < LTm1; t++) {
        k_dec_gates<<<64, 256>>>(t, dec_Wih, dec_Whh);
        k_skinny<<<64, 256>>>(0, t, attn_W, 1536, nullptr, 0);      // q = h @ Wq^T
        k_dec_attn<<<64, 256>>>(attn_v);
        k_skinny<<<32, 256>>>(1, t, lin_W, 1536, lin_b, 1);          // o = tanh([ctx,h]@lin^T+b)
    }

    // output projection + NLL
    k_tgt<<<376, 256>>>(ts, out_W, out_b);
    k_lse<<<dim3(NCHUNK, NROWS_PAD / 128), 256>>>(out_W, out_b);
    k_red1<<<12, 256>>>();
    k_red2<<<1, 32>>>((float*)d_out);
}

// round 4
// speedup vs baseline: 1.0744x; 1.0744x over previous
#include <cuda_runtime.h>
#include <math.h>

#define LS 48
#define LTm1 47
#define NB 64      // batch
#define E 512
#define H 512
#define VT 32000
#define NROWS 3008      // 47*64 decoder (step,batch) rows
#define NROWS_PAD 3072  // padded to multiple of 128
#define NCHUNK 250      // 32000/128

// ---------------- device scratch (static, allowed) ----------------
__device__ float g_zero[NB * H];
__device__ float g_embs_src[LS * NB * E];
__device__ float g_embs_tgt[LTm1 * NB * E];
__device__ float g_Xf[LS * NB * 2048];
__device__ float g_Xb[LS * NB * 2048];
__device__ float g_Gd[LTm1 * NB * 2048];
__device__ float g_hs[LS * NB * 1024];    // [t][b][1024] fwd||bwd
__device__ float g_hsp[LS * NB * 1024];   // hs_proj [l][b][1024]
__device__ float g_cf[NB * H];
__device__ float g_cb[NB * H];
__device__ float g_cd[NB * H];
__device__ float g_od[NB * H];
__device__ float g_q[NB * 1024];
__device__ float g_ctx[NB * 1024];
__device__ float g_H[NROWS_PAD * H];      // decoder h history (rows m=t*64+b)
__device__ float g_tgt_logit[NROWS];
__device__ float g_maskv[NROWS];
__device__ float g_partial[NROWS_PAD * NCHUNK];
__device__ float g_blk[24];

__device__ __forceinline__ float sigm(float x) { return 1.f / (1.f + __expf(-x)); }

// fp32->tf32 round-to-nearest (keep as b32 pattern inside a float slot)
__device__ __forceinline__ float f2tf(float x) {
    unsigned u;
    asm("cvt.rna.tf32.f32 %0, %1;" : "=r"(u) : "f"(x));
    return __uint_as_float(u);
}

// fast exp on the FMA pipe (no MUFU): exp(x) = 2^(x*log2e), Taylor deg-5 on frac
__device__ __forceinline__ float fexp(float x) {
    float y = x * 1.44269504f;
    float fl = floorf(y);
    float f = y - fl;
    float p = fmaf(f, 0.0013333558f, 0.0096181291f);
    p = fmaf(f, p, 0.055504109f);
    p = fmaf(f, p, 0.24022651f);
    p = fmaf(f, p, 0.69314718f);
    p = fmaf(f, p, 1.0f);
    int e = (int)fl;
    return p * __int_as_float((e + 127) << 23);
}

__device__ __forceinline__ void mma_tf32(float* c, unsigned a0, unsigned a1, unsigned a2,
                                         unsigned a3, unsigned b0, unsigned b1) {
    asm volatile(
        "mma.sync.aligned.m16n8k8.row.col.f32.tf32.tf32.f32 "
        "{%0,%1,%2,%3},{%4,%5,%6,%7},{%8,%9},{%0,%1,%2,%3};"
        : "+f"(c[0]), "+f"(c[1]), "+f"(c[2]), "+f"(c[3])
        : "r"(a0), "r"(a1), "r"(a2), "r"(a3), "r"(b0), "r"(b1));
}

// ---------------- init: zero states + H padding ----------------
__global__ void k_init() {
    int i = blockIdx.x * blockDim.x + threadIdx.x;
    int n = NB * H;
    for (int j = i; j < n; j += gridDim.x * blockDim.x) {
        g_zero[j] = 0.f; g_cf[j] = 0.f; g_cb[j] = 0.f;
        g_cd[j] = 0.f; g_od[j] = 0.f;
        g_H[NROWS * H + j] = 0.f;   // pad rows 3008..3071 (exactly NB*H elems)
    }
}

// ---------------- embedding gather ----------------
__global__ void k_gather(const int* __restrict__ tok, const float* __restrict__ emb, int mode) {
    float* out = mode ? g_embs_tgt : g_embs_src;
    int rows = mode ? (LTm1 * NB) : (LS * NB);
    int n4 = rows * (E / 4);
    const float4* e4 = (const float4*)emb;
    float4* o4 = (float4*)out;
    for (int j = blockIdx.x * blockDim.x + threadIdx.x; j < n4; j += gridDim.x * blockDim.x) {
        int r = j >> 7;       // E/4 = 128
        int c = j & 127;
        o4[j] = e4[(size_t)tok[r] * 128 + c];
    }
}

// ---------------- generic 64x64 SGEMM: C = A @ W^T + b1 + b2 ----------------
__global__ void __launch_bounds__(256) k_sgemm64(int mode, const float* __restrict__ W, int ldw,
                                                 const float* __restrict__ b1, const float* __restrict__ b2,
                                                 int K) {
    __shared__ float As[16][64];
    __shared__ float Bs[16][64];
    const float* A; int lda; float* C; int ldc;
    switch (mode) {
        case 0: A = g_embs_src; lda = E;    C = g_Xf;  ldc = 2048; break;
        case 1: A = g_embs_src; lda = E;    C = g_Xb;  ldc = 2048; break;
        case 2: A = g_embs_tgt; lda = E;    C = g_Gd;  ldc = 2048; break;
        default: A = g_hs;      lda = 1024; C = g_hsp; ldc = 1024; break;
    }
    int nb = blockIdx.x, mb = blockIdx.y;
    int tid = threadIdx.x;
    int tx = tid & 15, ty = tid >> 4;
    const float* Ab = A + (size_t)mb * 64 * lda;
    const float* Wb = W + (size_t)nb * 64 * ldw;
    float acc[4][4] = {};
    for (int kb = 0; kb < K; kb += 16) {
#pragma unroll
        for (int i = 0; i < 4; i++) {
            int e = tid + 256 * i;
            int kk = e & 15, r = e >> 4;
            As[kk][r] = Ab[(size_t)r * lda + kb + kk];
            Bs[kk][r] = Wb[(size_t)r * ldw + kb + kk];
        }
        __syncthreads();
#pragma unroll
        for (int kk = 0; kk < 16; kk++) {
            float a[4], w[4];
#pragma unroll
            for (int i = 0; i < 4; i++) a[i] = As[kk][ty * 4 + i];
#pragma unroll
            for (int j = 0; j < 4; j++) w[j] = Bs[kk][tx * 4 + j];
#pragma unroll
            for (int i = 0; i < 4; i++)
#pragma unroll
                for (int j = 0; j < 4; j++) acc[i][j] += a[i] * w[j];
        }
        __syncthreads();
    }
#pragma unroll
    for (int i = 0; i < 4; i++) {
        int r = mb * 64 + ty * 4 + i;
#pragma unroll
        for (int j = 0; j < 4; j++) {
            int n = nb * 64 + tx * 4 + j;
            float v = acc[i][j];
            if (b1) v += b1[n];
            if (b2) v += b2[n];
            C[(size_t)r * ldc + n] = v;
        }
    }
}

// ---------------- encoder step (both directions), fused gates + cell ----------------
__global__ void __launch_bounds__(256) k_enc_step(int t, const float* __restrict__ Whh_f,
                                                  const float* __restrict__ Whh_b) {
    __shared__ float As[16][64];
    __shared__ float Bs[16][32];
    __shared__ float gbuf[64][33];
    int dir = blockIdx.y;
    int cu = blockIdx.x * 8;
    int tid = threadIdx.x;
    const float* Whh = dir ? Whh_b : Whh_f;
    const float* hprev; int ldh;
    if (t == 0) { hprev = g_zero; ldh = H; }
    else if (dir == 0) { hprev = g_hs + (size_t)(t - 1) * NB * 1024; ldh = 1024; }
    else { hprev = g_hs + (size_t)(LS - t) * NB * 1024 + 512; ldh = 1024; }
    int tx = tid & 15, ty = tid >> 4;
    float acc[4][2] = {};
    for (int kb = 0; kb < H; kb += 16) {
#pragma unroll
        for (int i = 0; i < 4; i++) {
            int e = tid + 256 * i;
            int kk = e & 15, b = e >> 4;
            As[kk][b] = hprev[(size_t)b * ldh + kb + kk];
        }
#pragma unroll
        for (int i = 0; i < 2; i++) {
            int e = tid + 256 * i;
            int kk = e & 15, j = e >> 4;
            int row = ((j >> 3) << 9) + cu + (j & 7);
            Bs[kk][j] = Whh[(size_t)row * H + kb + kk];
        }
        __syncthreads();
#pragma unroll
        for (int kk = 0; kk < 16; kk++) {
            float a0 = As[kk][ty * 4 + 0], a1 = As[kk][ty * 4 + 1];
            float a2 = As[kk][ty * 4 + 2], a3 = As[kk][ty * 4 + 3];
            float w0 = Bs[kk][tx * 2 + 0], w1 = Bs[kk][tx * 2 + 1];
            acc[0][0] += a0 * w0; acc[0][1] += a0 * w1;
            acc[1][0] += a1 * w0; acc[1][1] += a1 * w1;
            acc[2][0] += a2 * w0; acc[2][1] += a2 * w1;
            acc[3][0] += a3 * w0; acc[3][1] += a3 * w1;
        }
        __syncthreads();
    }
#pragma unroll
    for (int i = 0; i < 4; i++)
#pragma unroll
        for (int j = 0; j < 2; j++)
            gbuf[ty * 4 + i][tx * 2 + j] = acc[i][j];
    __syncthreads();
    const float* Xg = dir ? (g_Xb + (size_t)(LS - 1 - t) * NB * 2048)
                          : (g_Xf + (size_t)t * NB * 2048);
    float* cst = dir ? g_cb : g_cf;
    float* hs_out = dir ? (g_hs + (size_t)(LS - 1 - t) * NB * 1024 + 512)
                        : (g_hs + (size_t)t * NB * 1024);
#pragma unroll
    for (int i = 0; i < 2; i++) {
        int cid = tid + 256 * i;
        int b = cid >> 3, cl = cid & 7;
        int cell = cu + cl;
        const float* xb = Xg + (size_t)b * 2048;
        float gi = gbuf[b][cl] + xb[cell];
        float gf = gbuf[b][8 + cl] + xb[512 + cell];
        float gg = gbuf[b][16 + cl] + xb[1024 + cell];
        float go = gbuf[b][24 + cl] + xb[1536 + cell];
        float co = cst[b * H + cell];
        float cn = sigm(gf) * co + sigm(gi) * tanhf(gg);
        float hn = sigm(go) * tanhf(cn);
        cst[b * H + cell] = cn;
        hs_out[(size_t)b * 1024 + cell] = hn;
    }
}

// ---------------- decoder gates ----------------
__global__ void __launch_bounds__(256) k_dec_gates(int t, const float* __restrict__ Wih,
                                                   const float* __restrict__ Whh) {
    __shared__ float As[16][64];
    __shared__ float Bs[16][32];
    __shared__ float gbuf[64][33];
    int cu = blockIdx.x * 8;
    int tid = threadIdx.x;
    int tx = tid & 15, ty = tid >> 4;
    const float* hprev = (t == 0) ? g_zero : (g_H + (size_t)(t - 1) * NB * H);
    float acc[4][2] = {};
    for (int part = 0; part < 2; part++) {
        const float* Ain = (part == 0) ? g_od : hprev;
        for (int kb = 0; kb < H; kb += 16) {
#pragma unroll
            for (int i = 0; i < 4; i++) {
                int e = tid + 256 * i;
                int kk = e & 15, b = e >> 4;
                As[kk][b] = Ain[(size_t)b * H + kb + kk];
            }
#pragma unroll
            for (int i = 0; i < 2; i++) {
                int e = tid + 256 * i;
                int kk = e & 15, j = e >> 4;
                int row = ((j >> 3) << 9) + cu + (j & 7);
                Bs[kk][j] = (part == 0) ? Wih[(size_t)row * 1024 + 512 + kb + kk]
                                        : Whh[(size_t)row * H + kb + kk];
            }
            __syncthreads();
#pragma unroll
            for (int kk = 0; kk < 16; kk++) {
                float a0 = As[kk][ty * 4 + 0], a1 = As[kk][ty * 4 + 1];
                float a2 = As[kk][ty * 4 + 2], a3 = As[kk][ty * 4 + 3];
                float w0 = Bs[kk][tx * 2 + 0], w1 = Bs[kk][tx * 2 + 1];
                acc[0][0] += a0 * w0; acc[0][1] += a0 * w1;
                acc[1][0] += a1 * w0; acc[1][1] += a1 * w1;
                acc[2][0] += a2 * w0; acc[2][1] += a2 * w1;
                acc[3][0] += a3 * w0; acc[3][1] += a3 * w1;
            }
            __syncthreads();
        }
    }
#pragma unroll
    for (int i = 0; i < 4; i++)
#pragma unroll
        for (int j = 0; j < 2; j++)
            gbuf[ty * 4 + i][tx * 2 + j] = acc[i][j];
    __syncthreads();
    const float* Xg = g_Gd + (size_t)t * NB * 2048;
#pragma unroll
    for (int i = 0; i < 2; i++) {
        int cid = tid + 256 * i;
        int b = cid >> 3, cl = cid & 7;
        int cell = cu + cl;
        const float* xb = Xg + (size_t)b * 2048;
        float gi = gbuf[b][cl] + xb[cell];
        float gf = gbuf[b][8 + cl] + xb[512 + cell];
        float gg = gbuf[b][16 + cl] + xb[1024 + cell];
        float go = gbuf[b][24 + cl] + xb[1536 + cell];
        float co = g_cd[b * H + cell];
        float cn = sigm(gf) * co + sigm(gi) * tanhf(gg);
        float hn = sigm(go) * tanhf(cn);
        g_cd[b * H + cell] = cn;
        g_H[((size_t)t * NB + b) * H + cell] = hn;
    }
}

// ---------------- skinny GEMM (M=64) ----------------
__global__ void __launch_bounds__(256) k_skinny(int mode, int t, const float* __restrict__ W, int ldw,
                                                const float* __restrict__ bias, int doTanh) {
    __shared__ float As[32][64];
    __shared__ float Ws[16][32];
    const float *A1, *A2 = nullptr; int lda1, lda2 = H, K1, K2; float* out; int ldo;
    if (mode == 0) { A1 = g_H + (size_t)t * NB * H; lda1 = H; K1 = H; K2 = 0; out = g_q; ldo = 1024; }
    else { A1 = g_ctx; lda1 = 1024; K1 = 1024; A2 = g_H + (size_t)t * NB * H; K2 = H; out = g_od; ldo = H; }
    int tid = threadIdx.x;
    int tn = tid & 15, tb = tid >> 4;
    int n0 = blockIdx.x * 16;
    float acc[4] = {};
    int KT = K1 + K2;
    for (int k0 = 0; k0 < KT; k0 += 32) {
        const float* src; int lda; int col;
        if (k0 < K1) { src = A1; lda = lda1; col = k0; }
        else { src = A2; lda = lda2; col = k0 - K1; }
#pragma unroll
        for (int i = 0; i < 8; i++) {
            int e = tid + 256 * i;
            int kk = e & 31, b = e >> 5;
            As[kk][b] = src[(size_t)b * lda + col + kk];
        }
#pragma unroll
        for (int i = 0; i < 2; i++) {
            int e = tid + 256 * i;
            int kk = e & 31, j = e >> 5;
            Ws[j][kk] = W[(size_t)(n0 + j) * ldw + k0 + kk];
        }
        __syncthreads();
#pragma unroll
        for (int kk = 0; kk < 32; kk++) {
            float w = Ws[tn][kk];
#pragma unroll
            for (int i = 0; i < 4; i++) acc[i] += As[kk][tb * 4 + i] * w;
        }
        __syncthreads();
    }
    int n = n0 + tn;
    float bv = bias ? bias[n] : 0.f;
#pragma unroll
    for (int i = 0; i < 4; i++) {
        float v = acc[i] + bv;
        if (doTanh) v = tanhf(v);
        out[(size_t)(tb * 4 + i) * ldo + n] = v;
    }
}

// ---------------- attention: score+softmax+context, one block per batch ----------------
__global__ void __launch_bounds__(256) k_dec_attn(const float* __restrict__ v) {
    __shared__ float sq[1024];
    __shared__ float sv[1024];
    __shared__ float sps[LS];
    int b = blockIdx.x, tid = threadIdx.x;
#pragma unroll
    for (int i = 0; i < 4; i++) {
        int k = tid + 256 * i;
        sq[k] = g_q[b * 1024 + k];
        sv[k] = v[k];
    }
    __syncthreads();
    int wid = tid >> 5, lane = tid & 31;
    for (int l = wid; l < LS; l += 8) {
        const float* hp = g_hsp + ((size_t)l * NB + b) * 1024;
        float s = 0.f;
        for (int k = lane; k < 1024; k += 32) s += sv[k] * tanhf(hp[k] + sq[k]);
#pragma unroll
        for (int o = 16; o; o >>= 1) s += __shfl_down_sync(0xffffffff, s, o);
        if (lane == 0) sps[l] = s;
    }
    __syncthreads();
    if (tid == 0) {
        float mx = -1e30f;
        for (int l = 0; l < LS; l++) mx = fmaxf(mx, sps[l]);
        float sm = 0.f;
        for (int l = 0; l < LS; l++) { float e = __expf(sps[l] - mx); sps[l] = e; sm += e; }
        float inv = 1.f / sm;
        for (int l = 0; l < LS; l++) sps[l] *= inv;
    }
    __syncthreads();
#pragma unroll
    for (int i = 0; i < 4; i++) {
        int k = tid + 256 * i;
        float acc = 0.f;
        for (int l = 0; l < LS; l++) acc += sps[l] * g_hs[((size_t)l * NB + b) * 1024 + k];
        g_ctx[b * 1024 + k] = acc;
    }
}

// ---------------- target logits (one warp per row) ----------------
__global__ void k_tgt(const int* __restrict__ ts, const float* __restrict__ oW,
                      const float* __restrict__ ob) {
    int gw = blockIdx.x * 8 + (threadIdx.x >> 5);
    int lane = threadIdx.x & 31;
    if (gw >= NROWS) return;
    int tok = ts[gw + NB];
    const float* h = g_H + (size_t)gw * H;
    const float* w = oW + (size_t)tok * H;
    float s = 0.f;
    for (int k = lane; k < H; k += 32) s += h[k] * w[k];
#pragma unroll
    for (int o = 16; o; o >>= 1) s += __shfl_down_sync(0xffffffff, s, o);
    if (lane == 0) {
        g_tgt_logit[gw] = s + ob[tok];
        g_maskv[gw] = (tok != 0) ? 1.f : 0.f;
    }
}

// ---------------- tf32 tensor-core GEMM + fused exp row-sums ----------------
// H(3072x512) @ out_W^T(512x32000); block tile 128x128, 8 warps (warp tile 32x64).
__global__ void __launch_bounds__(256) k_lse(const float* __restrict__ oW,
                                             const float* __restrict__ ob) {
    __shared__ float As[16][132];
    __shared__ float Bs[16][132];
    __shared__ float red[128][8];
    int nb = blockIdx.x, mb = blockIdx.y;
    int tid = threadIdx.x;
    int lane = tid & 31, wid = tid >> 5;
    int wm = wid & 3, wn = wid >> 2;
    int mo = wm * 32, no = wn * 64;

    const float* Ab = g_H + (size_t)mb * 128 * H;
    const float* Wb = oW + (size_t)nb * 128 * H;

    int r0 = tid >> 2, q0 = tid & 3;               // element 0
    int r1 = (tid + 256) >> 2, q1 = (tid + 256) & 3; // element 1

    float c[2][8][4];
#pragma unroll
    for (int mt = 0; mt < 2; mt++)
#pragma unroll
        for (int nt = 0; nt < 8; nt++)
#pragma unroll
            for (int j = 0; j < 4; j++) c[mt][nt][j] = 0.f;

    // prefetch first tile
    float4 pa0 = *(const float4*)&Ab[(size_t)r0 * H + q0 * 4];
    float4 pa1 = *(const float4*)&Ab[(size_t)r1 * H + q1 * 4];
    float4 pb0 = *(const float4*)&Wb[(size_t)r0 * H + q0 * 4];
    float4 pb1 = *(const float4*)&Wb[(size_t)r1 * H + q1 * 4];

    for (int kb = 0; kb < H; kb += 16) {
        As[q0 * 4 + 0][r0] = f2tf(pa0.x); As[q0 * 4 + 1][r0] = f2tf(pa0.y);
        As[q0 * 4 + 2][r0] = f2tf(pa0.z); As[q0 * 4 + 3][r0] = f2tf(pa0.w);
        As[q1 * 4 + 0][r1] = f2tf(pa1.x); As[q1 * 4 + 1][r1] = f2tf(pa1.y);
        As[q1 * 4 + 2][r1] = f2tf(pa1.z); As[q1 * 4 + 3][r1] = f2tf(pa1.w);
        Bs[q0 * 4 + 0][r0] = f2tf(pb0.x); Bs[q0 * 4 + 1][r0] = f2tf(pb0.y);
        Bs[q0 * 4 + 2][r0] = f2tf(pb0.z); Bs[q0 * 4 + 3][r0] = f2tf(pb0.w);
        Bs[q1 * 4 + 0][r1] = f2tf(pb1.x); Bs[q1 * 4 + 1][r1] = f2tf(pb1.y);
        Bs[q1 * 4 + 2][r1] = f2tf(pb1.z); Bs[q1 * 4 + 3][r1] = f2tf(pb1.w);
        __syncthreads();

        int kn = kb + 16;
        if (kn < H) {
            pa0 = *(const float4*)&Ab[(size_t)r0 * H + kn + q0 * 4];
            pa1 = *(const float4*)&Ab[(size_t)r1 * H + kn + q1 * 4];
            pb0 = *(const float4*)&Wb[(size_t)r0 * H + kn + q0 * 4];
            pb1 = *(const float4*)&Wb[(size_t)r1 * H + kn + q1 * 4];
        }

#pragma unroll
        for (int ks = 0; ks < 16; ks += 8) {
            unsigned a[2][4];
#pragma unroll
            for (int mt = 0; mt < 2; mt++) {
                int mc = mo + mt * 16 + (lane >> 2);
                a[mt][0] = __float_as_uint(As[ks + (lane & 3)][mc]);
                a[mt][1] = __float_as_uint(As[ks + (lane & 3)][mc + 8]);
                a[mt][2] = __float_as_uint(As[ks + 4 + (lane & 3)][mc]);
                a[mt][3] = __float_as_uint(As[ks + 4 + (lane & 3)][mc + 8]);
            }
#pragma unroll
            for (int nt = 0; nt < 8; nt++) {
                int nc = no + nt * 8 + (lane >> 2);
                unsigned b0 = __float_as_uint(Bs[ks + (lane & 3)][nc]);
                unsigned b1 = __float_as_uint(Bs[ks + 4 + (lane & 3)][nc]);
                mma_tf32(c[0][nt], a[0][0], a[0][1], a[0][2], a[0][3], b0, b1);
                mma_tf32(c[1][nt], a[1][0], a[1][1], a[1][2], a[1][3], b0, b1);
            }
        }
        __syncthreads();
    }

    // biases for this thread's 16 columns
    float bv0[8], bv1[8];
#pragma unroll
    for (int nt = 0; nt < 8; nt++) {
        int n = nb * 128 + no + nt * 8 + 2 * (lane & 3);
        bv0[nt] = ob[n];
        bv1[nt] = ob[n + 1];
    }

    // exp + per-row partial sums
#pragma unroll
    for (int mt = 0; mt < 2; mt++) {
        float slo = 0.f, shi = 0.f;
#pragma unroll
        for (int nt = 0; nt < 8; nt++) {
            slo += fexp(c[mt][nt][0] + bv0[nt]) + fexp(c[mt][nt][1] + bv1[nt]);
            shi += fexp(c[mt][nt][2] + bv0[nt]) + fexp(c[mt][nt][3] + bv1[nt]);
        }
        int rlo = mo + mt * 16 + (lane >> 2);
        red[rlo][wn * 4 + (lane & 3)] = slo;
        red[rlo + 8][wn * 4 + (lane & 3)] = shi;
    }
    __syncthreads();
    if (tid < 128) {
        float s = 0.f;
#pragma unroll
        for (int x = 0; x < 8; x++) s += red[tid][x];
        g_partial[((size_t)mb * 128 + tid) * NCHUNK + nb] = s;
    }
}

// ---------------- final reductions ----------------
__global__ void k_red1() {
    __shared__ float s1[256], s2[256];
    int m = blockIdx.x * 256 + threadIdx.x;
    float v = 0.f, mk = 0.f;
    if (m < NROWS) {
        float s = 0.f;
        const float* p = g_partial + (size_t)m * NCHUNK;
        for (int c = 0; c < NCHUNK; c++) s += p[c];
        mk = g_maskv[m];
        v = (logf(s) - g_tgt_logit[m]) * mk;
    }
    s1[threadIdx.x] = v; s2[threadIdx.x] = mk;
    __syncthreads();
    for (int o = 128; o; o >>= 1) {
        if (threadIdx.x < o) { s1[threadIdx.x] += s1[threadIdx.x + o]; s2[threadIdx.x] += s2[threadIdx.x + o]; }
        __syncthreads();
    }
    if (threadIdx.x == 0) { g_blk[blockIdx.x * 2] = s1[0]; g_blk[blockIdx.x * 2 + 1] = s2[0]; }
}

__global__ void k_red2(float* out) {
    if (threadIdx.x == 0) {
        float a = 0.f, b = 0.f;
        for (int i = 0; i < 12; i++) { a += g_blk[i * 2]; b += g_blk[i * 2 + 1]; }
        out[0] = a / b;
    }
}

// ---------------- launcher ----------------
extern "C" void kernel_launch(void* const* d_in, const int* in_sizes, int n_in,
                              void* d_out, int out_size) {
    const int* xs = (const int*)d_in[0];
    const int* ts = (const int*)d_in[1];
    const float* src_emb = (const float*)d_in[2];
    const float* tgt_emb = (const float*)d_in[3];
    const float* encf_Wih = (const float*)d_in[4];
    const float* encf_Whh = (const float*)d_in[5];
    const float* encf_bih = (const float*)d_in[6];
    const float* encf_bhh = (const float*)d_in[7];
    const float* encb_Wih = (const float*)d_in[8];
    const float* encb_Whh = (const float*)d_in[9];
    const float* encb_bih = (const float*)d_in[10];
    const float* encb_bhh = (const float*)d_in[11];
    const float* dec_Wih = (const float*)d_in[12];
    const float* dec_Whh = (const float*)d_in[13];
    const float* dec_bih = (const float*)d_in[14];
    const float* dec_bhh = (const float*)d_in[15];
    const float* attn_W = (const float*)d_in[16];
    const float* attn_v = (const float*)d_in[17];
    const float* lin_W = (const float*)d_in[18];
    const float* lin_b = (const float*)d_in[19];
    const float* out_W = (const float*)d_in[20];
    const float* out_b = (const float*)d_in[21];

    k_init<<<64, 256>>>();
    k_gather<<<1024, 256>>>(xs, src_emb, 0);
    k_gather<<<1024, 256>>>(ts, tgt_emb, 1);

    // input-gate precompute GEMMs
    k_sgemm64<<<dim3(32, 48), 256>>>(0, encf_Wih, 512, encf_bih, encf_bhh, 512);
    k_sgemm64<<<dim3(32, 48), 256>>>(1, encb_Wih, 512, encb_bih, encb_bhh, 512);
    k_sgemm64<<<dim3(32, 47), 256>>>(2, dec_Wih, 1024, dec_bih, dec_bhh, 512);

    // encoder recurrence (both directions per launch)
    for (int t = 0; t < LS; t++)
        k_enc_step<<<dim3(64, 2), 256>>>(t, encf_Whh, encb_Whh);

    // hs_proj = hs @ Wk^T   (Wk = attn_W[:, 512:], ld 1536)
    k_sgemm64<<<dim3(16, 48), 256>>>(3, attn_W + 512, 1536, nullptr, nullptr, 1024);

    // decoder recurrence
    for (int t = 0; t < LTm1; t++) {
        k_dec_gates<<<64, 256>>>(t, dec_Wih, dec_Whh);
        k_skinny<<<64, 256>>>(0, t, attn_W, 1536, nullptr, 0);      // q = h @ Wq^T
        k_dec_attn<<<64, 256>>>(attn_v);
        k_skinny<<<32, 256>>>(1, t, lin_W, 1536, lin_b, 1);          // o = tanh([ctx,h]@lin^T+b)
    }

    // output projection + NLL
    k_tgt<<<376, 256>>>(ts, out_W, out_b);
    k_lse<<<dim3(NCHUNK, NROWS_PAD / 128), 256>>>(out_W, out_b);
    k_red1<<<12, 256>>>();
    k_red2<<<1, 32>>>((float*)d_out);
}